// round 16
// baseline (speedup 1.0000x reference)
#include <cuda_runtime.h>
#include <cuda_fp16.h>
#include <stdint.h>
#include <math.h>

#define BB 16
#define NN 1024
#define FF 512

// ---------------- scratch (__device__ globals; no allocs allowed) ----------
__device__ float g_r[BB * NN];
__device__ __half g_adjT[BB * NN * NN];        // [b][i][j] = adj[b][j][i], fp16
__device__ __half g_hst[BB * FF * NN];         // HsT [b][f][j], fp16
__device__ __half g_xb[BB * NN * FF];          // activations [b][node][f], fp16
__device__ __half g_wt[3 * FF * FF];           // W^T per layer [f][k], fp16

// ---------------- base-ISA PTX helpers -------------------------------------
__device__ __forceinline__ uint32_t smem_u32(const void* p) {
    uint32_t a;
    asm("{ .reg .u64 t; cvta.to.shared.u64 t, %1; cvt.u32.u64 %0, t; }"
        : "=r"(a) : "l"(p));
    return a;
}
__device__ __forceinline__ void cp16(uint32_t s, const void* g) {
    asm volatile("cp.async.cg.shared.global [%0], [%1], 16;" :: "r"(s), "l"(g));
}
#define CP_COMMIT() asm volatile("cp.async.commit_group;" ::: "memory")
#define CP_WAIT1() asm volatile("cp.async.wait_group 1;" ::: "memory")

__device__ __forceinline__ void ldsm4(uint32_t* r, uint32_t addr) {
    asm volatile("ldmatrix.sync.aligned.m8n8.x4.shared.b16 {%0,%1,%2,%3}, [%4];"
        : "=r"(r[0]), "=r"(r[1]), "=r"(r[2]), "=r"(r[3]) : "r"(addr));
}
__device__ __forceinline__ void mma_f16(float* c, const uint32_t* a,
                                        const uint32_t* b) {
    asm volatile(
        "mma.sync.aligned.m16n8k16.row.col.f32.f16.f16.f32 "
        "{%0,%1,%2,%3}, {%4,%5,%6,%7}, {%8,%9}, {%0,%1,%2,%3};"
        : "+f"(c[0]), "+f"(c[1]), "+f"(c[2]), "+f"(c[3])
        : "r"(a[0]), "r"(a[1]), "r"(a[2]), "r"(a[3]), "r"(b[0]), "r"(b[1]));
}
__device__ __forceinline__ uint32_t sw128(uint32_t x) { return x ^ ((x >> 3) & 0x70); }

// SMEM: A (16KB, 128 rows) + B (16KB, 128 rows) per stage; 3 stages = 96KB/CTA
// Epilogue staging reuses the same 96KB (padded tile: fp16 272B/row, fp32 528B/row)
#define T_A  0
#define T_B  16384
#define STAGE 32768
#define NSTAGE 3
#define SMEM_TOTAL (NSTAGE * STAGE)
#define NTHREADS 128
#define PITCH16 272
#define PITCH32 528

// ---------------------------------------------------------------------------
// transpose to single fp16: out[z][C][R] = fp16(in[z][R][C])
__global__ void transpose_half(const float* __restrict__ in,
                               __half* __restrict__ oh, int R, int C) {
    __shared__ float t[32][33];
    const int i0 = blockIdx.x * 32, j0 = blockIdx.y * 32;
    const size_t zb = (size_t)blockIdx.z * R * C;
    const int tx = threadIdx.x, ty = threadIdx.y;
#pragma unroll
    for (int q = 0; q < 4; q++) {
        int j = j0 + ty + q * 8;
        t[ty + q * 8][tx] = in[zb + (size_t)j * C + i0 + tx];
    }
    __syncthreads();
#pragma unroll
    for (int q = 0; q < 4; q++) {
        int i = i0 + ty + q * 8;
        oh[zb + (size_t)i * R + j0 + tx] = __float2half(t[tx][ty + q * 8]);
    }
}

// r from adjT row sums: colsum[b,i] = sum_j adjT[b][i][j]  (contiguous fp16)
__global__ void rowsum_r(const __half* __restrict__ adjT, float* __restrict__ r) {
    const int row = blockIdx.x * 8 + (threadIdx.x >> 5);   // 0 .. BB*NN-1
    const int lane = threadIdx.x & 31;
    const uint4* p = (const uint4*)(adjT + (size_t)row * NN);
    float s = 0.f;
#pragma unroll
    for (int k = 0; k < 4; k++) {
        uint4 v = p[lane + k * 32];
        const __half2* h = (const __half2*)&v;
#pragma unroll
        for (int e = 0; e < 4; e++) {
            float2 f = __half22float2(h[e]);
            s += f.x + f.y;
        }
    }
#pragma unroll
    for (int off = 16; off > 0; off >>= 1)
        s += __shfl_xor_sync(0xFFFFFFFFu, s, off);
    if (lane == 0) r[row] = (s > 0.f) ? rsqrtf(s) : 0.f;
}

// transpose all three W matrices in one launch (z selects layer)
__global__ void transpose_w3(const float* __restrict__ W1,
                             const float* __restrict__ W2,
                             const float* __restrict__ W3,
                             __half* __restrict__ oh) {
    __shared__ float t[32][33];
    const int i0 = blockIdx.x * 32, j0 = blockIdx.y * 32;
    const int z = blockIdx.z;
    const float* in = (z == 0) ? W1 : (z == 1) ? W2 : W3;
    __half* outp = oh + (size_t)z * FF * FF;
    const int tx = threadIdx.x, ty = threadIdx.y;
#pragma unroll
    for (int q = 0; q < 4; q++) {
        int j = j0 + ty + q * 8;
        t[ty + q * 8][tx] = in[(size_t)j * FF + i0 + tx];
    }
    __syncthreads();
#pragma unroll
    for (int q = 0; q < 4; q++) {
        int i = i0 + ty + q * 8;
        outp[(size_t)i * FF + j0 + tx] = __float2half(t[tx][ty + q * 8]);
    }
}

// elementwise fp32 -> fp16 convert (float4 vectorized)
__global__ void convert_half(const float* __restrict__ in,
                             __half* __restrict__ oh, int n4) {
    int i = blockIdx.x * 256 + threadIdx.x;
    if (i >= n4) return;
    float4 v = ((const float4*)in)[i];
    ((__half2*)oh)[i * 2 + 0] = __halves2half2(__float2half(v.x), __float2half(v.y));
    ((__half2*)oh)[i * 2 + 1] = __halves2half2(__float2half(v.z), __float2half(v.w));
}

// ---------------------------------------------------------------------------
// HMMA GEMM: D[128m x 128n] = sum_k A[m,k]*B[n,k]   (fp16 in, fp32 acc)
//   128 threads (4 warps, 2x2 grid, warp tile 64x64), K-chunk 64,
//   3-stage cp.async pipeline, 2 CTAs/SM, SMEM-staged coalesced epilogue.
//   mode 0: out = r[n]*D                -> HsT fp16 (m=f, n=j)
//   mode 1: out = relu(r[m]*D+bias[n])  -> Xb fp16  (m=i, n=f)
//   mode 2: out = r[m]*D+bias[n]        -> fp32     (m=i, n=f)
// ---------------------------------------------------------------------------
__global__ void __launch_bounds__(NTHREADS, 2)
gcn_gemm(const __half* __restrict__ Aop, const __half* __restrict__ Bop,
         const float* __restrict__ r, const float* __restrict__ bias,
         int lda, size_t aBatch, int ldb, size_t bBatch, int nk, int mode,
         float* __restrict__ outF, __half* __restrict__ oH) {
    extern __shared__ char smem[];
    const uint32_t smb = smem_u32(smem);
    const int tid = threadIdx.x, lane = tid & 31, wid = tid >> 5;
    const int b = blockIdx.z;
    const int m0 = blockIdx.y * 128;
    const int n0 = blockIdx.x * 128;
    const int wr = wid & 1, wc = wid >> 1;      // 2x2 warp grid
    const int m0w = wr * 64, n0w = wc * 64;

    const __half* aP = Aop + b * aBatch + (size_t)m0 * lda;
    const __half* bP = Bop + b * bBatch + (size_t)n0 * ldb;

    auto load_stage = [&](int kc, int buf) {
        const uint32_t sb = smb + buf * STAGE;
#pragma unroll
        for (int i = 0; i < 8; i++) {           // A: 1024 chunk16s
            const int chunk = i * NTHREADS + tid;
            const int row = chunk >> 3, c16 = chunk & 7;
            const uint32_t so = sw128((uint32_t)row * 128 + c16 * 16);
            cp16(sb + T_A + so, aP + (size_t)row * lda + kc * 64 + c16 * 8);
        }
#pragma unroll
        for (int i = 0; i < 8; i++) {           // B: 1024 chunk16s
            const int chunk = i * NTHREADS + tid;
            const int row = chunk >> 3, c16 = chunk & 7;
            const uint32_t so = sw128((uint32_t)row * 128 + c16 * 16);
            cp16(sb + T_B + so, bP + (size_t)row * ldb + kc * 64 + c16 * 8);
        }
    };

    const uint32_t rowA = (uint32_t)(m0w + (lane & 15)) * 128 + (lane >> 4) * 16;
    const uint32_t rowB = (uint32_t)(n0w + ((lane >> 4) << 3) + (lane & 7)) * 128 +
                          ((lane >> 3) & 1) * 16;

    float acc[4][8][4];
#pragma unroll
    for (int a = 0; a < 4; a++)
#pragma unroll
        for (int c = 0; c < 8; c++)
#pragma unroll
            for (int d = 0; d < 4; d++) acc[a][c][d] = 0.f;

    load_stage(0, 0);
    CP_COMMIT();
    if (nk > 1) load_stage(1, 1);
    CP_COMMIT();

    int buf = 0;
    for (int s = 0; s < nk; s++) {
        CP_WAIT1();
        __syncthreads();
        if (s + 2 < nk) load_stage(s + 2, (buf + 2) % NSTAGE);
        CP_COMMIT();

        const uint32_t sb = smb + buf * STAGE;
#pragma unroll
        for (int kt = 0; kt < 4; kt++) {
            uint32_t Af[4][4], Bf[4][4];
#pragma unroll
            for (int mi = 0; mi < 4; mi++)
                ldsm4(Af[mi], sb + T_A + sw128(rowA + mi * 2048 + kt * 32));
#pragma unroll
            for (int n2 = 0; n2 < 4; n2++)
                ldsm4(Bf[n2], sb + T_B + sw128(rowB + n2 * 2048 + kt * 32));
#pragma unroll
            for (int mi = 0; mi < 4; mi++)
#pragma unroll
                for (int ni = 0; ni < 8; ni++)
                    mma_f16(acc[mi][ni], Af[mi], &Bf[ni >> 1][(ni & 1) * 2]);
        }
        buf = (buf + 1) % NSTAGE;
    }

    // ---------------- epilogue (SMEM-staged, coalesced) --------------------
    const int g = lane >> 2, cp2 = (lane & 3) * 2;
    const float* rr = r + b * NN;

    __syncthreads();    // all warps past their last ldsm before smem reuse

    if (mode != 2) {
        // stage fp16 tile: 128 rows x 128 cols, pitch PITCH16 bytes
#pragma unroll
        for (int mi = 0; mi < 4; mi++)
#pragma unroll
            for (int h = 0; h < 2; h++) {
                const int row = m0w + mi * 16 + g + h * 8;
                const float scM = (mode == 1) ? rr[m0 + row] : 0.f;
#pragma unroll
                for (int ni = 0; ni < 8; ni++) {
                    const int col = n0w + ni * 8 + cp2;
                    float v0, v1;
                    if (mode == 0) {
                        v0 = acc[mi][ni][h * 2 + 0] * rr[n0 + col];
                        v1 = acc[mi][ni][h * 2 + 1] * rr[n0 + col + 1];
                    } else {
                        v0 = fmaxf(scM * acc[mi][ni][h * 2 + 0] + bias[n0 + col], 0.f);
                        v1 = fmaxf(scM * acc[mi][ni][h * 2 + 1] + bias[n0 + col + 1], 0.f);
                    }
                    *(__half2*)(smem + row * PITCH16 + col * 2) =
                        __halves2half2(__float2half(v0), __float2half(v1));
                }
            }
        __syncthreads();
        // coalesced copy-out: 128 rows x 256B, 16B chunks
        char* dst;
        size_t pitch;
        if (mode == 0) {
            dst = (char*)oH + (((size_t)b * FF + m0) * NN + n0) * 2;
            pitch = (size_t)NN * 2;
        } else {
            dst = (char*)oH + (((size_t)b * NN + m0) * FF + n0) * 2;
            pitch = (size_t)FF * 2;
        }
#pragma unroll
        for (int it = 0; it < 16; it++) {
            const int c = it * NTHREADS + tid;
            const int row = c >> 4, off = (c & 15) * 16;
            uint4 v = *(uint4*)(smem + row * PITCH16 + off);
            *(uint4*)(dst + (size_t)row * pitch + off) = v;
        }
    } else {
        // stage fp32 tile: 128 rows x 128 cols, pitch PITCH32 bytes
#pragma unroll
        for (int mi = 0; mi < 4; mi++)
#pragma unroll
            for (int h = 0; h < 2; h++) {
                const int row = m0w + mi * 16 + g + h * 8;
                const float scM = rr[m0 + row];
#pragma unroll
                for (int ni = 0; ni < 8; ni++) {
                    const int col = n0w + ni * 8 + cp2;
                    float2 v;
                    v.x = scM * acc[mi][ni][h * 2 + 0] + bias[n0 + col];
                    v.y = scM * acc[mi][ni][h * 2 + 1] + bias[n0 + col + 1];
                    *(float2*)(smem + row * PITCH32 + col * 4) = v;
                }
            }
        __syncthreads();
        char* dst = (char*)outF + (((size_t)b * NN + m0) * FF + n0) * 4;
        const size_t pitch = (size_t)FF * 4;
#pragma unroll
        for (int it = 0; it < 32; it++) {
            const int c = it * NTHREADS + tid;
            const int row = c >> 5, off = (c & 31) * 16;
            uint4 v = *(uint4*)(smem + row * PITCH32 + off);
            *(uint4*)(dst + (size_t)row * pitch + off) = v;
        }
    }
}

// ---------------------------------------------------------------------------
extern "C" void kernel_launch(void* const* d_in, const int* in_sizes, int n_in,
                              void* d_out, int out_size) {
    const float* X0  = (const float*)d_in[0];
    const float* adj = (const float*)d_in[1];
    const float* W1  = (const float*)d_in[2];
    const float* b1  = (const float*)d_in[3];
    const float* W2  = (const float*)d_in[4];
    const float* b2  = (const float*)d_in[5];
    const float* W3  = (const float*)d_in[6];
    const float* b3  = (const float*)d_in[7];
    float* out = (float*)d_out;

    float* r;
    __half *atp, *hst, *xb, *wt;
    cudaGetSymbolAddress((void**)&r,   g_r);
    cudaGetSymbolAddress((void**)&atp, g_adjT);
    cudaGetSymbolAddress((void**)&hst, g_hst);
    cudaGetSymbolAddress((void**)&xb,  g_xb);
    cudaGetSymbolAddress((void**)&wt,  g_wt);

    cudaFuncSetAttribute(gcn_gemm, cudaFuncAttributeMaxDynamicSharedMemorySize,
                         SMEM_TOTAL);

    // prep
    transpose_half<<<dim3(32, 32, BB), dim3(32, 8)>>>(adj, atp, NN, NN);  // 0
    rowsum_r<<<BB * NN / 8, 256>>>(atp, r);                               // 1
    transpose_w3<<<dim3(16, 16, 3), dim3(32, 8)>>>(W1, W2, W3, wt);       // 2
    convert_half<<<BB * NN * FF / 4 / 256, 256>>>(X0, xb, BB * NN * FF / 4); // 3

    const dim3 g1(NN / 128, FF / 128, BB);   // GEMM1: HsT[f,j]  (8,4,16)
    const dim3 g2(FF / 128, NN / 128, BB);   // GEMM2: Y[i,f]    (4,8,16)
    const float* biases[3] = {b1, b2, b3};

    for (int l = 0; l < 3; l++) {
        // GEMM1: A = W^T [f][k] (lda=FF), B = Xb [j][k] (ldb=FF)
        gcn_gemm<<<g1, NTHREADS, SMEM_TOTAL>>>(
            wt + l * FF * FF, xb, r, (const float*)0,
            FF, (size_t)0, FF, (size_t)NN * FF, FF / 64, 0,
            (float*)0, hst);
        // GEMM2: A = adjT [i][j] (lda=NN), B = HsT [f][j] (ldb=NN)
        const int mode = (l == 2) ? 2 : 1;
        gcn_gemm<<<g2, NTHREADS, SMEM_TOTAL>>>(
            atp, hst, r, biases[l],
            NN, (size_t)NN * NN, NN, (size_t)FF * NN, NN / 64, mode,
            out, xb);
    }
}

// round 17
// speedup vs baseline: 1.4941x; 1.4941x over previous
#include <cuda_runtime.h>
#include <cuda_fp16.h>
#include <stdint.h>
#include <math.h>

#define BB 16
#define NN 1024
#define FF 512

// ---------------- scratch (__device__ globals; no allocs allowed) ----------
__device__ float g_r[BB * NN];
__device__ __half g_adjT[BB * NN * NN];        // [b][i][j] = adj[b][j][i], fp16
__device__ __half g_hst[BB * FF * NN];         // HsT [b][f][j], fp16
__device__ __half g_xb[BB * NN * FF];          // activations [b][node][f], fp16
__device__ __half g_wt[3 * FF * FF];           // W^T per layer [f][k], fp16

// ---------------- base-ISA PTX helpers -------------------------------------
__device__ __forceinline__ uint32_t smem_u32(const void* p) {
    uint32_t a;
    asm("{ .reg .u64 t; cvta.to.shared.u64 t, %1; cvt.u32.u64 %0, t; }"
        : "=r"(a) : "l"(p));
    return a;
}
__device__ __forceinline__ void cp16(uint32_t s, const void* g) {
    asm volatile("cp.async.cg.shared.global [%0], [%1], 16;" :: "r"(s), "l"(g));
}
#define CP_COMMIT() asm volatile("cp.async.commit_group;" ::: "memory")
#define CP_WAIT1() asm volatile("cp.async.wait_group 1;" ::: "memory")

__device__ __forceinline__ void ldsm4(uint32_t* r, uint32_t addr) {
    asm volatile("ldmatrix.sync.aligned.m8n8.x4.shared.b16 {%0,%1,%2,%3}, [%4];"
        : "=r"(r[0]), "=r"(r[1]), "=r"(r[2]), "=r"(r[3]) : "r"(addr));
}
__device__ __forceinline__ void mma_f16(float* c, const uint32_t* a,
                                        const uint32_t* b) {
    asm volatile(
        "mma.sync.aligned.m16n8k16.row.col.f32.f16.f16.f32 "
        "{%0,%1,%2,%3}, {%4,%5,%6,%7}, {%8,%9}, {%0,%1,%2,%3};"
        : "+f"(c[0]), "+f"(c[1]), "+f"(c[2]), "+f"(c[3])
        : "r"(a[0]), "r"(a[1]), "r"(a[2]), "r"(a[3]), "r"(b[0]), "r"(b[1]));
}
__device__ __forceinline__ uint32_t sw128(uint32_t x) { return x ^ ((x >> 3) & 0x70); }

// SMEM: A (16KB, 128 rows) + B (16KB, 128 rows) per stage; 3 stages = 96KB/CTA
#define T_A  0
#define T_B  16384
#define STAGE 32768
#define NSTAGE 3
#define SMEM_TOTAL (NSTAGE * STAGE)
#define NTHREADS 128

// ---------------------------------------------------------------------------
// transpose to single fp16: out[z][C][R] = fp16(in[z][R][C])
__global__ void transpose_half(const float* __restrict__ in,
                               __half* __restrict__ oh, int R, int C) {
    __shared__ float t[32][33];
    const int i0 = blockIdx.x * 32, j0 = blockIdx.y * 32;
    const size_t zb = (size_t)blockIdx.z * R * C;
    const int tx = threadIdx.x, ty = threadIdx.y;
#pragma unroll
    for (int q = 0; q < 4; q++) {
        int j = j0 + ty + q * 8;
        t[ty + q * 8][tx] = in[zb + (size_t)j * C + i0 + tx];
    }
    __syncthreads();
#pragma unroll
    for (int q = 0; q < 4; q++) {
        int i = i0 + ty + q * 8;
        oh[zb + (size_t)i * R + j0 + tx] = __float2half(t[tx][ty + q * 8]);
    }
}

// r from adjT row sums: colsum[b,i] = sum_j adjT[b][i][j]  (contiguous fp16)
__global__ void rowsum_r(const __half* __restrict__ adjT, float* __restrict__ r) {
    const int row = blockIdx.x * 8 + (threadIdx.x >> 5);   // 0 .. BB*NN-1
    const int lane = threadIdx.x & 31;
    const uint4* p = (const uint4*)(adjT + (size_t)row * NN);
    float s = 0.f;
#pragma unroll
    for (int k = 0; k < 4; k++) {
        uint4 v = p[lane + k * 32];
        const __half2* h = (const __half2*)&v;
#pragma unroll
        for (int e = 0; e < 4; e++) {
            float2 f = __half22float2(h[e]);
            s += f.x + f.y;
        }
    }
#pragma unroll
    for (int off = 16; off > 0; off >>= 1)
        s += __shfl_xor_sync(0xFFFFFFFFu, s, off);
    if (lane == 0) r[row] = (s > 0.f) ? rsqrtf(s) : 0.f;
}

// transpose all three W matrices in one launch (z selects layer)
__global__ void transpose_w3(const float* __restrict__ W1,
                             const float* __restrict__ W2,
                             const float* __restrict__ W3,
                             __half* __restrict__ oh) {
    __shared__ float t[32][33];
    const int i0 = blockIdx.x * 32, j0 = blockIdx.y * 32;
    const int z = blockIdx.z;
    const float* in = (z == 0) ? W1 : (z == 1) ? W2 : W3;
    __half* outp = oh + (size_t)z * FF * FF;
    const int tx = threadIdx.x, ty = threadIdx.y;
#pragma unroll
    for (int q = 0; q < 4; q++) {
        int j = j0 + ty + q * 8;
        t[ty + q * 8][tx] = in[(size_t)j * FF + i0 + tx];
    }
    __syncthreads();
#pragma unroll
    for (int q = 0; q < 4; q++) {
        int i = i0 + ty + q * 8;
        outp[(size_t)i * FF + j0 + tx] = __float2half(t[tx][ty + q * 8]);
    }
}

// elementwise fp32 -> fp16 convert (float4 vectorized)
__global__ void convert_half(const float* __restrict__ in,
                             __half* __restrict__ oh, int n4) {
    int i = blockIdx.x * 256 + threadIdx.x;
    if (i >= n4) return;
    float4 v = ((const float4*)in)[i];
    ((__half2*)oh)[i * 2 + 0] = __halves2half2(__float2half(v.x), __float2half(v.y));
    ((__half2*)oh)[i * 2 + 1] = __halves2half2(__float2half(v.z), __float2half(v.w));
}

// ---------------------------------------------------------------------------
// HMMA GEMM: D[128m x 128n] = sum_k A[m,k]*B[n,k]   (fp16 in, fp32 acc)
//   128 threads (4 warps, 2x2 grid, warp tile 64x64), K-chunk 64,
//   3-stage cp.async pipeline, 2 CTAs/SM for stall interleaving.
//   mode 0: out = r[n]*D                -> HsT fp16 (m=f, n=j)
//   mode 1: out = relu(r[m]*D+bias[n])  -> Xb fp16  (m=i, n=f)
//   mode 2: out = r[m]*D+bias[n]        -> fp32     (m=i, n=f)
// ---------------------------------------------------------------------------
__global__ void __launch_bounds__(NTHREADS, 2)
gcn_gemm(const __half* __restrict__ Aop, const __half* __restrict__ Bop,
         const float* __restrict__ r, const float* __restrict__ bias,
         int lda, size_t aBatch, int ldb, size_t bBatch, int nk, int mode,
         float* __restrict__ outF, __half* __restrict__ oH) {
    extern __shared__ char smem[];
    const uint32_t smb = smem_u32(smem);
    const int tid = threadIdx.x, lane = tid & 31, wid = tid >> 5;
    const int b = blockIdx.z;
    const int m0 = blockIdx.y * 128;
    const int n0 = blockIdx.x * 128;
    const int wr = wid & 1, wc = wid >> 1;      // 2x2 warp grid
    const int m0w = wr * 64, n0w = wc * 64;

    const __half* aP = Aop + b * aBatch + (size_t)m0 * lda;
    const __half* bP = Bop + b * bBatch + (size_t)n0 * ldb;

    auto load_stage = [&](int kc, int buf) {
        const uint32_t sb = smb + buf * STAGE;
#pragma unroll
        for (int i = 0; i < 8; i++) {           // A: 1024 chunk16s
            const int chunk = i * NTHREADS + tid;
            const int row = chunk >> 3, c16 = chunk & 7;
            const uint32_t so = sw128((uint32_t)row * 128 + c16 * 16);
            cp16(sb + T_A + so, aP + (size_t)row * lda + kc * 64 + c16 * 8);
        }
#pragma unroll
        for (int i = 0; i < 8; i++) {           // B: 1024 chunk16s
            const int chunk = i * NTHREADS + tid;
            const int row = chunk >> 3, c16 = chunk & 7;
            const uint32_t so = sw128((uint32_t)row * 128 + c16 * 16);
            cp16(sb + T_B + so, bP + (size_t)row * ldb + kc * 64 + c16 * 8);
        }
    };

    const uint32_t rowA = (uint32_t)(m0w + (lane & 15)) * 128 + (lane >> 4) * 16;
    const uint32_t rowB = (uint32_t)(n0w + ((lane >> 4) << 3) + (lane & 7)) * 128 +
                          ((lane >> 3) & 1) * 16;

    float acc[4][8][4];
#pragma unroll
    for (int a = 0; a < 4; a++)
#pragma unroll
        for (int c = 0; c < 8; c++)
#pragma unroll
            for (int d = 0; d < 4; d++) acc[a][c][d] = 0.f;

    load_stage(0, 0);
    CP_COMMIT();
    if (nk > 1) load_stage(1, 1);
    CP_COMMIT();

    int buf = 0;
    for (int s = 0; s < nk; s++) {
        CP_WAIT1();
        __syncthreads();
        if (s + 2 < nk) {
            int nbuf = buf + 2;
            if (nbuf >= NSTAGE) nbuf -= NSTAGE;
            load_stage(s + 2, nbuf);
        }
        CP_COMMIT();

        const uint32_t sb = smb + buf * STAGE;
#pragma unroll
        for (int kt = 0; kt < 4; kt++) {
            uint32_t Af[4][4], Bf[4][4];
#pragma unroll
            for (int mi = 0; mi < 4; mi++)
                ldsm4(Af[mi], sb + T_A + sw128(rowA + mi * 2048 + kt * 32));
#pragma unroll
            for (int n2 = 0; n2 < 4; n2++)
                ldsm4(Bf[n2], sb + T_B + sw128(rowB + n2 * 2048 + kt * 32));
#pragma unroll
            for (int mi = 0; mi < 4; mi++)
#pragma unroll
                for (int ni = 0; ni < 8; ni++)
                    mma_f16(acc[mi][ni], Af[mi], &Bf[ni >> 1][(ni & 1) * 2]);
        }
        if (++buf == NSTAGE) buf = 0;
    }

    // ---------------- epilogue (hoisted r/bias loads) ----------------------
    const int g = lane >> 2, cp2 = (lane & 3) * 2;
    const float* rr = r + b * NN;

    if (mode == 0) {
        float rj[16];
#pragma unroll
        for (int ni = 0; ni < 8; ni++) {
            rj[ni * 2 + 0] = rr[n0 + n0w + ni * 8 + cp2];
            rj[ni * 2 + 1] = rr[n0 + n0w + ni * 8 + cp2 + 1];
        }
#pragma unroll
        for (int mi = 0; mi < 4; mi++)
#pragma unroll
            for (int h = 0; h < 2; h++) {
                const int f = m0 + m0w + mi * 16 + g + h * 8;
                const size_t rowb = ((size_t)b * FF + f) * NN;
#pragma unroll
                for (int ni = 0; ni < 8; ni++) {
                    const int j = n0 + n0w + ni * 8 + cp2;
                    float v0 = acc[mi][ni][h * 2 + 0] * rj[ni * 2 + 0];
                    float v1 = acc[mi][ni][h * 2 + 1] * rj[ni * 2 + 1];
                    *(__half2*)(oH + rowb + j) =
                        __halves2half2(__float2half(v0), __float2half(v1));
                }
            }
    } else if (mode == 1) {
        float bf[16];
#pragma unroll
        for (int ni = 0; ni < 8; ni++) {
            bf[ni * 2 + 0] = bias[n0 + n0w + ni * 8 + cp2];
            bf[ni * 2 + 1] = bias[n0 + n0w + ni * 8 + cp2 + 1];
        }
#pragma unroll
        for (int mi = 0; mi < 4; mi++)
#pragma unroll
            for (int h = 0; h < 2; h++) {
                const int i = m0 + m0w + mi * 16 + g + h * 8;
                const float sc = rr[i];
                const size_t rowb = ((size_t)b * NN + i) * FF;
#pragma unroll
                for (int ni = 0; ni < 8; ni++) {
                    const int f = n0 + n0w + ni * 8 + cp2;
                    float v0 = fmaxf(sc * acc[mi][ni][h * 2 + 0] + bf[ni * 2 + 0], 0.f);
                    float v1 = fmaxf(sc * acc[mi][ni][h * 2 + 1] + bf[ni * 2 + 1], 0.f);
                    *(__half2*)(oH + rowb + f) =
                        __halves2half2(__float2half(v0), __float2half(v1));
                }
            }
    } else {
        float bf[16];
#pragma unroll
        for (int ni = 0; ni < 8; ni++) {
            bf[ni * 2 + 0] = bias[n0 + n0w + ni * 8 + cp2];
            bf[ni * 2 + 1] = bias[n0 + n0w + ni * 8 + cp2 + 1];
        }
#pragma unroll
        for (int mi = 0; mi < 4; mi++)
#pragma unroll
            for (int h = 0; h < 2; h++) {
                const int i = m0 + m0w + mi * 16 + g + h * 8;
                const float sc = rr[i];
                const size_t rowb = ((size_t)b * NN + i) * FF;
#pragma unroll
                for (int ni = 0; ni < 8; ni++) {
                    const int f = n0 + n0w + ni * 8 + cp2;
                    float2 v;
                    v.x = sc * acc[mi][ni][h * 2 + 0] + bf[ni * 2 + 0];
                    v.y = sc * acc[mi][ni][h * 2 + 1] + bf[ni * 2 + 1];
                    *(float2*)(outF + rowb + f) = v;
                }
            }
    }
}

// ---------------------------------------------------------------------------
extern "C" void kernel_launch(void* const* d_in, const int* in_sizes, int n_in,
                              void* d_out, int out_size) {
    const float* X0  = (const float*)d_in[0];
    const float* adj = (const float*)d_in[1];
    const float* W1  = (const float*)d_in[2];
    const float* b1  = (const float*)d_in[3];
    const float* W2  = (const float*)d_in[4];
    const float* b2  = (const float*)d_in[5];
    const float* W3  = (const float*)d_in[6];
    const float* b3  = (const float*)d_in[7];
    float* out = (float*)d_out;

    float* r;
    __half *atp, *hst, *xb, *wt;
    cudaGetSymbolAddress((void**)&r,   g_r);
    cudaGetSymbolAddress((void**)&atp, g_adjT);
    cudaGetSymbolAddress((void**)&hst, g_hst);
    cudaGetSymbolAddress((void**)&xb,  g_xb);
    cudaGetSymbolAddress((void**)&wt,  g_wt);

    cudaFuncSetAttribute(gcn_gemm, cudaFuncAttributeMaxDynamicSharedMemorySize,
                         SMEM_TOTAL);

    // prep
    transpose_half<<<dim3(32, 32, BB), dim3(32, 8)>>>(adj, atp, NN, NN);  // 0
    rowsum_r<<<BB * NN / 8, 256>>>(atp, r);                               // 1
    transpose_w3<<<dim3(16, 16, 3), dim3(32, 8)>>>(W1, W2, W3, wt);       // 2
    convert_half<<<BB * NN * FF / 4 / 256, 256>>>(X0, xb, BB * NN * FF / 4); // 3

    const dim3 g1(NN / 128, FF / 128, BB);   // GEMM1: HsT[f,j]  (8,4,16)
    const dim3 g2(FF / 128, NN / 128, BB);   // GEMM2: Y[i,f]    (4,8,16)
    const float* biases[3] = {b1, b2, b3};

    for (int l = 0; l < 3; l++) {
        // GEMM1: A = W^T [f][k] (lda=FF), B = Xb [j][k] (ldb=FF)
        gcn_gemm<<<g1, NTHREADS, SMEM_TOTAL>>>(
            wt + l * FF * FF, xb, r, (const float*)0,
            FF, (size_t)0, FF, (size_t)NN * FF, FF / 64, 0,
            (float*)0, hst);
        // GEMM2: A = adjT [i][j] (lda=NN), B = HsT [f][j] (ldb=NN)
        const int mode = (l == 2) ? 2 : 1;
        gcn_gemm<<<g2, NTHREADS, SMEM_TOTAL>>>(
            atp, hst, r, biases[l],
            NN, (size_t)NN * NN, NN, (size_t)FF * NN, NN / 64, mode,
            out, xb);
    }
}